// round 16
// baseline (speedup 1.0000x reference)
#include <cuda_runtime.h>
#include <cuda_fp16.h>
#include <cstdint>

// ---------------------------------------------------------------------------
// RNNWithMarkovNet — fp16 HMMA logits + time-parallel Markov scan
//   latent (8192, 32768) f32 | vocab_w (32000,128) f32 | vocab_b (32000) f32
//   zi (32) i32 | y (32,256) i32  ->  yp (32,256) f32
// Scan parallelized over t: att_{32j} precomputed via T^32 (5 squarings),
// then 256 CTAs (batch x 8 segments) each run 32 exact steps.
// Logits: z stored as fp16(z*log2e), bias pre-scaled -> epilogue uses bare
// ex2.approx (no per-logit FMUL).
// ---------------------------------------------------------------------------

#define NBATCH 32
#define EDIM   128
#define TSTEP  256
#define VDIM   32000
#define NROWS  (NBATCH * TSTEP)   // 8192
#define VSPLIT 16000
#define NCHUNK 125                // 16000 / 128
#define NSUB   8
#define CPS    16
#define ZEPS   1e-6f
#define LOG2E  1.44269504088896341f

__device__ float g_zs[NROWS * EDIM];                     // (b,t) order, f32
__device__ __align__(128) __half g_zh[NROWS * EDIM];     // t-major, fp16, *log2e
__device__ __align__(128) __half g_wh[VDIM * EDIM];      // vocab fp16
__device__ float g_T[NBATCH * 64 * 64];                  // xtran per batch
__device__ float g_astart[NBATCH * 8 * 64];              // att at t=32j
__device__ float g_ps2[2 * NSUB * NROWS];                // partial sumexp
__device__ float g_ptot[NROWS];                          // total sumexp (t-major)
__device__ int   g_skip[64];                             // per-tile skip flag

__device__ __forceinline__ unsigned smem_u32(const void* p) {
    unsigned r;
    asm("{ .reg .u64 t; cvta.to.shared.u64 t, %1; cvt.u32.u64 %0, t; }"
        : "=r"(r) : "l"(p));
    return r;
}

__device__ __forceinline__ float ex2f(float x) {
    float y;
    asm("ex2.approx.f32 %0, %1;" : "=f"(y) : "f"(x));
    return y;
}

__device__ __forceinline__ void cpa16(uint32_t dst, const void* src) {
    asm volatile("cp.async.ca.shared.global [%0], [%1], 16;"
                 :: "r"(dst), "l"(src) : "memory");
}

#define LDM4(r, a)                                                            \
    asm volatile("ldmatrix.sync.aligned.m8n8.x4.shared.b16 {%0,%1,%2,%3}, [%4];" \
        : "=r"((r)[0]), "=r"((r)[1]), "=r"((r)[2]), "=r"((r)[3]) : "r"(a))

__device__ __forceinline__ void mma16816(float* d, const uint32_t* a,
                                         uint32_t b0, uint32_t b1) {
    asm volatile(
        "mma.sync.aligned.m16n8k16.row.col.f32.f16.f16.f32 "
        "{%0,%1,%2,%3}, {%4,%5,%6,%7}, {%8,%9}, {%0,%1,%2,%3};"
        : "+f"(d[0]), "+f"(d[1]), "+f"(d[2]), "+f"(d[3])
        : "r"(a[0]), "r"(a[1]), "r"(a[2]), "r"(a[3]), "r"(b0), "r"(b1));
}

// ===========================================================================
// Kernel 0: vocab_w f32 -> fp16 (unscaled; log2e lives on the z side)
// ===========================================================================
__global__ void convw_kernel(const float* __restrict__ vw) {
    int i = blockIdx.x * blockDim.x + threadIdx.x;
    float4 v = ((const float4*)vw)[i];
    *(__half2*)(g_wh + (size_t)i * 4)     = __floats2half2_rn(v.x, v.y);
    *(__half2*)(g_wh + (size_t)i * 4 + 2) = __floats2half2_rn(v.z, v.w);
}

// ===========================================================================
// Kernel 1a: scores + softmax -> T  (validated path), then T^32 via 5
// in-smem squarings, then 8 segment-start att vectors. 32 CTAs.
// ===========================================================================
#define TP_SMEM_FLOATS (64*128 + 64*129 + 64*64 + 64 + 64 + 64)

__global__ void transpow_kernel(const float* __restrict__ latent,
                                const int*   __restrict__ zi) {
    extern __shared__ float sm1[];
    float* sQ   = sm1;                 // 8192 ; later reused as squaring buf A
    float* sK   = sQ + 64 * 128;       // 8256 ; later reused as squaring buf B
    float* sT   = sK + 64 * 129;       // 4096 (T, stride 64)
    float* attA = sT + 64 * 64;
    float* attB = attA + 64;
    float* red  = attB + 64;

    const int b   = blockIdx.x;
    const int tid = threadIdx.x;
    const int g   = b >> 2;
    const size_t off = (size_t)(b & 3) * 8192;

    const size_t baseQ = (size_t)zi[g]      * 32768 + off;
    const size_t baseK = (size_t)zi[8 + g]  * 32768 + off;
    const size_t baseI = (size_t)zi[24 + g] * 32768 + off;

    for (int n = tid; n < 2048; n += 256) {
        *(float4*)(sQ + n * 4) = *(const float4*)(latent + baseQ + (size_t)n * 4);
    }
    for (int n = tid; n < 2048; n += 256) {
        int t  = n >> 5;
        int kq = (n & 31) * 4;
        float4 k = *(const float4*)(latent + baseK + (size_t)t * 128 + kq);
        float* d = sK + t * 129 + kq;
        d[0] = k.x; d[1] = k.y; d[2] = k.z; d[3] = k.w;
    }
    __syncthreads();

    const float scale = 0.08838834764831845f;
    for (int e = tid; e < 4096; e += 256) {
        int s = e >> 6, t = e & 63;
        const float* q = sQ + s * 128;
        const float* k = sK + t * 129;
        float a0 = 0.f, a1 = 0.f;
        #pragma unroll 8
        for (int kk = 0; kk < 128; kk += 2) {
            a0 += q[kk]     * k[kk];
            a1 += q[kk + 1] * k[kk + 1];
        }
        sT[e] = (a0 + a1) * scale;
    }
    __syncthreads();

    // column softmax over s -> xtran in sT ; gather xi col 0 for att0
    if (tid < 64) {
        int t = tid;
        float m = -INFINITY;
        for (int s = 0; s < 64; ++s) m = fmaxf(m, sT[s * 64 + t]);
        float sum = 0.f;
        for (int s = 0; s < 64; ++s) {
            float e = __expf(sT[s * 64 + t] - m);
            sT[s * 64 + t] = e;
            sum += e;
        }
        float inv = 1.f / sum;
        for (int s = 0; s < 64; ++s) sT[s * 64 + t] *= inv;
        red[t] = latent[baseI + (size_t)t * 128];
    }
    __syncthreads();

    // publish T for scan kernel
    for (int e = tid; e < 4096; e += 256) g_T[b * 4096 + e] = sT[e];

    if (tid < 64) {
        float m = -INFINITY;
        for (int s = 0; s < 64; ++s) m = fmaxf(m, red[s]);
        float sum = 0.f;
        for (int s = 0; s < 64; ++s) sum += __expf(red[s] - m);
        attA[tid] = __expf(red[tid] - m) / sum;
    }

    // copy T into stride-65 buffer (Q region free now)
    float* pa = sQ;        // 64*65 = 4160 <= 8192
    float* pb = sK;        // 64*65 = 4160 <= 8256
    __syncthreads();
    for (int e = tid; e < 4096; e += 256)
        pa[(e >> 6) * 65 + (e & 63)] = sT[e];
    __syncthreads();

    // 5 squarings: T^2, T^4, T^8, T^16, T^32
    for (int it = 0; it < 5; ++it) {
        for (int e = tid; e < 4096; e += 256) {
            int s = e >> 6, t = e & 63;
            const float* ra = pa + s * 65;
            const float* ca = pa + t;
            float a0 = 0.f, a1 = 0.f;
            #pragma unroll 8
            for (int k = 0; k < 64; k += 2) {
                a0 += ra[k]     * ca[k * 65];
                a1 += ra[k + 1] * ca[(k + 1) * 65];
            }
            pb[s * 65 + t] = a0 + a1;
        }
        __syncthreads();
        float* tmp = pa; pa = pb; pb = tmp;
    }
    // pa = T^32

    // segment starts: att_{32j}, j = 0..7
    float* cur = attA;
    float* nxt = attB;
    if (tid < 64) g_astart[(b * 8 + 0) * 64 + tid] = cur[tid];
    for (int j = 1; j < 8; ++j) {
        __syncthreads();
        if (tid < 64) {
            const float* c = pa + tid;
            float a0 = 0.f, a1 = 0.f;
            #pragma unroll 8
            for (int s = 0; s < 64; s += 2) {
                a0 += cur[s]     * c[s * 65];
                a1 += cur[s + 1] * c[(s + 1) * 65];
            }
            nxt[tid] = a0 + a1;
        }
        __syncthreads();
        float* tmp = cur; cur = nxt; nxt = tmp;
        if (tid < 64) g_astart[(b * 8 + j) * 64 + tid] = cur[tid];
    }
}

// ===========================================================================
// Kernel 1b: time-parallel scan. grid (32 batches, 8 segments), 256 thr.
// Each CTA: 32 exact steps from att_{32*seg}. Emits z (f32 b,t-order) and
// fp16(z*log2e) t-major.
// ===========================================================================
#define SC_SMEM_FLOATS (64*128 + 64*64 + 64 + 64)

__global__ void scan_kernel(const float* __restrict__ latent,
                            const int*   __restrict__ zi) {
    extern __shared__ float sm1[];
    float* sV   = sm1;                 // 64 x 128
    float* sT   = sV + 64 * 128;       // 64 x 64
    float* attA = sT + 64 * 64;
    float* attB = attA + 64;

    const int b   = blockIdx.x;
    const int seg = blockIdx.y;
    const int tid = threadIdx.x;
    const int g   = b >> 2;
    const size_t off = (size_t)(b & 3) * 8192;
    const size_t baseV = (size_t)zi[16 + g] * 32768 + off;

    for (int n = tid; n < 2048; n += 256)
        *(float4*)(sV + n * 4) = *(const float4*)(latent + baseV + (size_t)n * 4);
    for (int e = tid; e < 4096; e += 256)
        sT[e] = g_T[b * 4096 + e];
    if (tid < 64) attA[tid] = g_astart[(b * 8 + seg) * 64 + tid];
    __syncthreads();

    float* cur = attA;
    float* nxt = attB;
    const int t0 = seg * 32;
    float* zrow = g_zs + ((size_t)b * TSTEP + t0) * EDIM;

    for (int st = 0; st < 32; ++st) {
        if (tid < 128) {
            const float* v = sV + tid;
            float a0 = 0.f, a1 = 0.f;
            #pragma unroll 8
            for (int s = 0; s < 64; s += 2) {
                a0 += cur[s]     * v[s * 128];
                a1 += cur[s + 1] * v[(s + 1) * 128];
            }
            float z = a0 + a1;
            zrow[st * 128 + tid] = z;
            g_zh[((size_t)(t0 + st) * 32 + b) * 128 + tid] =
                __float2half_rn(z * LOG2E);
        } else if (tid < 192) {
            int tt = tid - 128;
            const float* w = sT + tt;
            float a0 = 0.f, a1 = 0.f;
            #pragma unroll 8
            for (int s = 0; s < 64; s += 2) {
                a0 += cur[s]     * w[s * 64];
                a1 += cur[s + 1] * w[(s + 1) * 64];
            }
            nxt[tt] = a0 + a1;
        }
        __syncthreads();
        float* tmp = cur; cur = nxt; nxt = tmp;
    }
}

// ===========================================================================
// Kernel F: per-tile redundancy flags (exact test vs computed row t=255).
// ===========================================================================
__global__ void flag_kernel() {
    const int tile = blockIdx.x;
    const int r    = threadIdx.x;
    const int t    = tile * 4 + (r >> 5);
    const int b    = r & 31;
    const float* zt = g_zs + ((size_t)b * TSTEP + t) * EDIM;
    const float* zr = g_zs + ((size_t)b * TSTEP + 255) * EDIM;
    float d = 0.f;
    #pragma unroll 4
    for (int e = 0; e < EDIM; ++e)
        d = fmaxf(d, fabsf(zt[e] - zr[e]));
    int all_red = __syncthreads_and(d < ZEPS);
    if (r == 0) g_skip[tile] = (tile == 63) ? 0 : all_red;
}

// ===========================================================================
// Kernel 2: fp16 HMMA logits GEMM + direct sumexp (ex2, pre-scaled inputs).
//   grid = (64 tiles x 2 splits, NSUB), 8 warps, warp tile 64x32, 2 CTAs/SM.
// ===========================================================================
#define PADB    272
#define A_BYTES (128 * PADB)           // 34816
#define SM_PS   0
#define SM_A    2048
#define SM_B    (SM_A + A_BYTES)
#define K2_SMEM (SM_B + 2 * A_BYTES)   // 106496

__device__ __forceinline__ void issue_b(uint32_t sbase, int tid, int split,
                                        int chunk, int buf) {
    const size_t r0 = ((size_t)split * VSPLIT + (size_t)chunk * 128) * 128;
    uint32_t d0 = sbase + SM_B + buf * A_BYTES;
    for (int g = tid; g < 2048; g += 256) {
        int row = g >> 4;
        int c16 = g & 15;
        cpa16(d0 + row * PADB + c16 * 16,
              g_wh + r0 + (size_t)row * 128 + c16 * 8);
    }
    asm volatile("cp.async.commit_group;" ::: "memory");
}

__global__ __launch_bounds__(256, 2)
void logits_kernel(const float* __restrict__ vb) {
    const int tile  = blockIdx.x >> 1;
    const int split = blockIdx.x & 1;
    const int sub   = blockIdx.y;
    if (g_skip[tile]) return;

    const int ch0 = sub * CPS;
    const int ch1 = (ch0 + CPS < NCHUNK) ? ch0 + CPS : NCHUNK;

    extern __shared__ char sm2[];
    const uint32_t sbase = smem_u32(sm2);
    float* sPS = (float*)(sm2 + SM_PS);

    const int tid  = threadIdx.x;
    const int lane = tid & 31;
    const int warp = tid >> 5;
    const int wm   = warp >> 2;
    const int wn   = warp & 3;

    {
        const size_t r0 = (size_t)tile * 128 * 128;
        for (int g = tid; g < 2048; g += 256) {
            int row = g >> 4;
            int c16 = g & 15;
            cpa16(sbase + SM_A + row * PADB + c16 * 16,
                  g_zh + r0 + (size_t)row * 128 + c16 * 8);
        }
    }
    issue_b(sbase, tid, split, ch0, 0);
    issue_b(sbase, tid, split, ch0 + 1, 1);

    const int l15   = lane & 15;
    const int khalf = (lane >> 4) * 16;
    const uint32_t aA   = sbase + SM_A + (uint32_t)(wm * 64 + l15) * PADB + khalf;
    const uint32_t bOff = (uint32_t)(wn * 32 + l15) * PADB + khalf;

    float rs[8];
    #pragma unroll
    for (int i = 0; i < 8; ++i) rs[i] = 0.f;

    for (int ch = ch0; ch < ch1; ++ch) {
        if (ch > ch0 && ch + 1 < ch1)
            issue_b(sbase, tid, split, ch + 1, (ch + 1) & 1);
        if (ch + 1 < ch1)
            asm volatile("cp.async.wait_group 1;" ::: "memory");
        else
            asm volatile("cp.async.wait_group 0;" ::: "memory");
        __syncthreads();

        const uint32_t bufb = sbase + SM_B + (ch & 1) * A_BYTES;

        float acc[4][4][4];
        #pragma unroll
        for (int mi = 0; mi < 4; ++mi)
            #pragma unroll
            for (int ni = 0; ni < 4; ++ni)
                #pragma unroll
                for (int c = 0; c < 4; ++c) acc[mi][ni][c] = 0.f;

        #pragma unroll
        for (int ks = 0; ks < 8; ++ks) {
            const uint32_t ka = ks * 32;
            uint32_t ah[4][4], bh[2][4];
            #pragma unroll
            for (int mi = 0; mi < 4; ++mi)
                LDM4(ah[mi], aA + mi * (16 * PADB) + ka);
            #pragma unroll
            for (int np = 0; np < 2; ++np)
                LDM4(bh[np], bufb + bOff + np * (16 * PADB) + ka);
            #pragma unroll
            for (int mi = 0; mi < 4; ++mi)
                #pragma unroll
                for (int ni = 0; ni < 4; ++ni) {
                    const int np = ni >> 1, sb = ni & 1;
                    mma16816(acc[mi][ni], ah[mi], bh[np][sb], bh[np][sb + 2]);
                }
        }

        // epilogue: acc is already logit*log2e ; bias scaled here once
        const float* bias = vb + split * VSPLIT + ch * 128 + wn * 32;
        #pragma unroll
        for (int ni = 0; ni < 4; ++ni) {
            const int bc = ni * 8 + (lane & 3) * 2;
            const float b0 = __ldg(bias + bc)     * LOG2E;
            const float b1 = __ldg(bias + bc + 1) * LOG2E;
            #pragma unroll
            for (int mi = 0; mi < 4; ++mi) {
                rs[mi * 2 + 0] += ex2f(acc[mi][ni][0] + b0)
                                + ex2f(acc[mi][ni][1] + b1);
                rs[mi * 2 + 1] += ex2f(acc[mi][ni][2] + b0)
                                + ex2f(acc[mi][ni][3] + b1);
            }
        }
        __syncthreads();
    }

    #pragma unroll
    for (int i = 0; i < 8; ++i) {
        rs[i] += __shfl_xor_sync(0xffffffffu, rs[i], 1);
        rs[i] += __shfl_xor_sync(0xffffffffu, rs[i], 2);
    }
    if ((lane & 3) == 0) {
        #pragma unroll
        for (int mi = 0; mi < 4; ++mi)
            #pragma unroll
            for (int h = 0; h < 2; ++h) {
                int row = wm * 64 + mi * 16 + (lane >> 2) + h * 8;
                sPS[wn * 128 + row] = rs[mi * 2 + h];
            }
    }
    __syncthreads();
    if (tid < 128) {
        float S = sPS[tid] + sPS[128 + tid] + sPS[256 + tid] + sPS[384 + tid];
        g_ps2[(sub * 2 + split) * NROWS + tile * 128 + tid] = S;
    }
}

// ===========================================================================
// Kernel R: reduce partial sumexps (skipped tiles -> row t=255, same batch)
// ===========================================================================
__global__ void reduce_kernel() {
    const int tile = blockIdx.x;
    const int rp   = tile * 128 + threadIdx.x;
    int src = rp;
    if (g_skip[tile]) src = 255 * 32 + (rp & 31);
    float S = 0.f;
    #pragma unroll
    for (int k = 0; k < 2 * NSUB; ++k)
        S += g_ps2[k * NROWS + src];
    g_ptot[rp] = S;
}

// ===========================================================================
// Kernel 3: target logit (exact f32) -> yp
// ===========================================================================
__global__ void combine_kernel(const float* __restrict__ vw,
                               const float* __restrict__ vb,
                               const int*   __restrict__ y,
                               float*       __restrict__ out) {
    int warp = (blockIdx.x * blockDim.x + threadIdx.x) >> 5;
    int lane = threadIdx.x & 31;
    if (warp >= NROWS) return;

    int tgt = y[warp];
    const float* z = g_zs + (size_t)warp * EDIM;
    const float* w = vw + (size_t)tgt * EDIM;
    float acc = 0.f;
    #pragma unroll
    for (int j = 0; j < 4; ++j)
        acc += z[lane + 32 * j] * w[lane + 32 * j];
    #pragma unroll
    for (int d = 16; d; d >>= 1)
        acc += __shfl_xor_sync(0xffffffffu, acc, d);

    if (lane == 0) {
        int b = warp >> 8, t = warp & 255;
        float tl = acc + vb[tgt];
        float S  = g_ptot[t * 32 + b];
        out[warp] = tl - logf(S);
    }
}

// ===========================================================================
extern "C" void kernel_launch(void* const* d_in, const int* in_sizes, int n_in,
                              void* d_out, int out_size) {
    const float* latent = (const float*)d_in[0];
    const float* vw     = (const float*)d_in[1];
    const float* vb     = (const float*)d_in[2];
    const int*   zi     = (const int*)d_in[3];
    const int*   y      = (const int*)d_in[4];
    float*       out    = (float*)d_out;

    const int tp_smem = TP_SMEM_FLOATS * (int)sizeof(float);  // ~83 KB
    const int sc_smem = SC_SMEM_FLOATS * (int)sizeof(float);  // ~50 KB

    cudaFuncSetAttribute(transpow_kernel,
                         cudaFuncAttributeMaxDynamicSharedMemorySize, tp_smem);
    cudaFuncSetAttribute(scan_kernel,
                         cudaFuncAttributeMaxDynamicSharedMemorySize, sc_smem);
    cudaFuncSetAttribute(logits_kernel,
                         cudaFuncAttributeMaxDynamicSharedMemorySize, K2_SMEM);

    convw_kernel<<<4000, 256>>>(vw);
    transpow_kernel<<<NBATCH, 256, tp_smem>>>(latent, zi);
    scan_kernel<<<dim3(NBATCH, 8), 256, sc_smem>>>(latent, zi);
    flag_kernel<<<64, 128>>>();
    logits_kernel<<<dim3(128, NSUB), 256, K2_SMEM>>>(vb);
    reduce_kernel<<<64, 128>>>();
    combine_kernel<<<1024, 256>>>(vw, vb, y, out);
}